// round 2
// baseline (speedup 1.0000x reference)
#include <cuda_runtime.h>

// EMA gated decomposition:
//   trend[b,0,c] = x[b,0,c]
//   trend[b,t,c] = 0.7*x[b,t,c] + 0.3*trend[b,t-1,c]
//   out = g*x + (1-2g)*trend,  g = clip(gate,0,1)
//
// Parallelization: the 0.3^k carry decays below fp32 ulp at k~32, so L=4096
// is split into 16 segments of 256 with a 32-step warm-up re-deriving the
// carry. One thread per (b, seg, float4-channel-group): 65536 threads,
// fully coalesced 128-bit accesses.

#define B_DIM 32
#define L_DIM 4096
#define C_DIM 512
#define C4    (C_DIM / 4)     // 128 float4 per (b,t) row
#define SEG   256
#define NSEG  (L_DIM / SEG)   // 16
#define LOOKBACK 32

__global__ __launch_bounds__(256) void ema_gate_kernel(
    const float4* __restrict__ x,
    const float*  __restrict__ gate,
    float4* __restrict__ out)
{
    int tid = blockIdx.x * blockDim.x + threadIdx.x;   // 0 .. 65535
    int c4  = tid & (C4 - 1);          // channel group (fastest -> coalesced)
    int rs  = tid >> 7;                // (b, seg)
    int seg = rs & (NSEG - 1);
    int b   = rs >> 4;

    float g  = fminf(fmaxf(*gate, 0.0f), 1.0f);
    float w1 = g;                 // coeff of x
    float w2 = 1.0f - 2.0f * g;   // coeff of trend
    const float AL = 0.7f, BE = 0.3f;

    int base = (b * L_DIM) * C4 + c4;  // max 16.7M, fits int
    int tstart = seg * SEG;
    int tend   = tstart + SEG;

    float4 h;
    int t;
    if (seg == 0) {
        // exact start: trend[0] = x[0]
        float4 v = x[base];
        h = v;
        float4 o;
        o.x = fmaf(w2, h.x, w1 * v.x);
        o.y = fmaf(w2, h.y, w1 * v.y);
        o.z = fmaf(w2, h.z, w1 * v.z);
        o.w = fmaf(w2, h.w, w1 * v.w);
        out[base] = o;
        t = 1;
    } else {
        // warm-up: seed carry LOOKBACK steps back; 0.3^32 ~ 2e-17 -> exact in fp32
        int t0 = tstart - LOOKBACK;
        h = x[base + t0 * C4];
        #pragma unroll 8
        for (int tw = t0 + 1; tw < tstart; ++tw) {
            float4 v = x[base + tw * C4];
            h.x = fmaf(AL, v.x, BE * h.x);
            h.y = fmaf(AL, v.y, BE * h.y);
            h.z = fmaf(AL, v.z, BE * h.z);
            h.w = fmaf(AL, v.w, BE * h.w);
        }
        t = tstart;
    }

    #pragma unroll 8
    for (; t < tend; ++t) {
        float4 v = x[base + t * C4];
        h.x = fmaf(AL, v.x, BE * h.x);
        h.y = fmaf(AL, v.y, BE * h.y);
        h.z = fmaf(AL, v.z, BE * h.z);
        h.w = fmaf(AL, v.w, BE * h.w);
        float4 o;
        o.x = fmaf(w2, h.x, w1 * v.x);
        o.y = fmaf(w2, h.y, w1 * v.y);
        o.z = fmaf(w2, h.z, w1 * v.z);
        o.w = fmaf(w2, h.w, w1 * v.w);
        out[base + t * C4] = o;
    }
}

extern "C" void kernel_launch(void* const* d_in, const int* in_sizes, int n_in,
                              void* d_out, int out_size)
{
    const float4* x    = (const float4*)d_in[0];
    const float*  gate = (const float*)d_in[1];
    float4* out        = (float4*)d_out;

    int total_threads = B_DIM * NSEG * C4;   // 65536
    int block = 256;
    int grid  = total_threads / block;       // 256
    ema_gate_kernel<<<grid, block>>>(x, gate, out);
}

// round 3
// speedup vs baseline: 1.1205x; 1.1205x over previous
#include <cuda_runtime.h>

// EMA gated decomposition:
//   trend[b,0,c] = x[b,0,c]
//   trend[b,t,c] = 0.7*x[b,t,c] + 0.3*trend[b,t-1,c]
//   out = g*x + (1-2g)*trend,  g = clip(gate,0,1)
//
// R2: SEG 256->128 (2x threads, occ ~41%) and LOOKBACK 32->16
// (0.3^16 ~ 4e-9 rel carry error, far under the 1e-3 threshold),
// keeping total HBM traffic within +0.2% of R1.

#define B_DIM 32
#define L_DIM 4096
#define C_DIM 512
#define C4    (C_DIM / 4)     // 128 float4 per (b,t) row
#define SEG   128
#define NSEG  (L_DIM / SEG)   // 32
#define LOOKBACK 16

__global__ __launch_bounds__(256) void ema_gate_kernel(
    const float4* __restrict__ x,
    const float*  __restrict__ gate,
    float4* __restrict__ out)
{
    int tid = blockIdx.x * blockDim.x + threadIdx.x;   // 0 .. 131071
    int c4  = tid & (C4 - 1);          // channel group (fastest -> coalesced)
    int rs  = tid >> 7;                // (b, seg)
    int seg = rs & (NSEG - 1);
    int b   = rs >> 5;

    float g  = fminf(fmaxf(*gate, 0.0f), 1.0f);
    float w1 = g;                 // coeff of x
    float w2 = 1.0f - 2.0f * g;   // coeff of trend
    const float AL = 0.7f, BE = 0.3f;

    int base = (b * L_DIM) * C4 + c4;
    int tstart = seg * SEG;
    int tend   = tstart + SEG;

    float4 h;
    int t;
    if (seg == 0) {
        // exact start: trend[0] = x[0]
        float4 v = x[base];
        h = v;
        float4 o;
        o.x = fmaf(w2, h.x, w1 * v.x);
        o.y = fmaf(w2, h.y, w1 * v.y);
        o.z = fmaf(w2, h.z, w1 * v.z);
        o.w = fmaf(w2, h.w, w1 * v.w);
        out[base] = o;
        t = 1;
    } else {
        // warm-up: seed carry LOOKBACK steps back; 0.3^16 ~ 4.3e-9 rel error
        int t0 = tstart - LOOKBACK;
        h = x[base + t0 * C4];
        #pragma unroll
        for (int tw = t0 + 1; tw < tstart; ++tw) {
            float4 v = x[base + tw * C4];
            h.x = fmaf(AL, v.x, BE * h.x);
            h.y = fmaf(AL, v.y, BE * h.y);
            h.z = fmaf(AL, v.z, BE * h.z);
            h.w = fmaf(AL, v.w, BE * h.w);
        }
        t = tstart;
    }

    #pragma unroll 8
    for (; t < tend; ++t) {
        float4 v = x[base + t * C4];
        h.x = fmaf(AL, v.x, BE * h.x);
        h.y = fmaf(AL, v.y, BE * h.y);
        h.z = fmaf(AL, v.z, BE * h.z);
        h.w = fmaf(AL, v.w, BE * h.w);
        float4 o;
        o.x = fmaf(w2, h.x, w1 * v.x);
        o.y = fmaf(w2, h.y, w1 * v.y);
        o.z = fmaf(w2, h.z, w1 * v.z);
        o.w = fmaf(w2, h.w, w1 * v.w);
        out[base + t * C4] = o;
    }
}

extern "C" void kernel_launch(void* const* d_in, const int* in_sizes, int n_in,
                              void* d_out, int out_size)
{
    const float4* x    = (const float4*)d_in[0];
    const float*  gate = (const float*)d_in[1];
    float4* out        = (float4*)d_out;

    int total_threads = B_DIM * NSEG * C4;   // 131072
    int block = 256;
    int grid  = total_threads / block;       // 512
    ema_gate_kernel<<<grid, block>>>(x, gate, out);
}